// round 10
// baseline (speedup 1.0000x reference)
#include <cuda_runtime.h>
#include <math.h>

#define B_    256
#define V_    128000
#define H_    200
#define TOPK  50
#define TOPSZ 64

constexpr float TOPP = 0.9f;
constexpr float TEMP = 0.6f;
constexpr float PEN  = 1.2f;

// ---------- streaming config ----------
#define SPLIT  16
#define TILE   (V_ / SPLIT)      // 8000 elements per block
#define TW     (TILE / 32)       // 250 mask words
#define NT     512
#define CAP    1024
constexpr float T0 = 5.2f;       // conservative static candidate threshold (adjusted units)

// ---------- fallback (exact two-pass) config ----------
#define NBINS   2048
#define BSHIFT  21
#define BPC     (NBINS / NT)
#define CAPF    2048
#define MASKW   (V_ / 32)
#define IDXMASK 0x1FFFF

// union workspace layout (bytes)
#define WS_BYTES 42624
#define FAST_WS  10240           // per-half fast-path workspace

// ---------- device scratch (static globals: zero-initialized at load) ----------
__device__ int   g_cnt[B_];
__device__ float g_cval[B_][CAP];
__device__ int   g_cidx[B_][CAP];

__device__ __forceinline__ unsigned ordu(float f) {
    unsigned u = __float_as_uint(f);
    return (u & 0x80000000u) ? ~u : (u | 0x80000000u);
}

#define BARH(h) asm volatile("bar.sync %0, %1;" :: "r"((h) + 1), "r"(256) : "memory")

// ============ K1: fused stream: read logits, penalty+temp, zero-fill out, collect candidates ============
__global__ __launch_bounds__(NT) void pass1_kernel(
    const float* __restrict__ logits,
    const int*   __restrict__ prev,
    float*       __restrict__ out)
{
    __shared__ unsigned sm_mask[TW];

    const int blk  = blockIdx.x;
    const int row  = blk >> 4;        // SPLIT = 16
    const int tile = blk & 15;
    const int base = tile * TILE;
    const int tid  = threadIdx.x;

    if (tid < TW) sm_mask[tid] = 0u;
    __syncthreads();
    for (int i = tid; i < H_; i += NT) {
        int t = __ldg(&prev[row * H_ + i]) - base;
        if ((unsigned)t < (unsigned)TILE)
            atomicOr(&sm_mask[((unsigned)t) >> 5], 1u << (t & 31));
    }
    __syncthreads();

    const float4* __restrict__ l4 = (const float4*)(logits + (size_t)row * V_ + base);
    float4* o4 = (float4*)(out + (size_t)row * V_ + base);
    const float4 z4 = make_float4(0.f, 0.f, 0.f, 0.f);

    #pragma unroll 8
    for (int i = tid; i < TILE / 4; i += NT) {
        float4 v = __ldcs(&l4[i]);
        int j = i << 2;
        unsigned mw = sm_mask[j >> 5];
        float a0 = v.x, a1 = v.y, a2 = v.z, a3 = v.w;
        if (mw != 0u) {                       // rare: ~12 of 8000 elements masked
            unsigned sh = j & 31;
            if ((mw >> (sh + 0)) & 1u) a0 = (a0 < 0.f) ? a0 * PEN : a0 / PEN;
            if ((mw >> (sh + 1)) & 1u) a1 = (a1 < 0.f) ? a1 * PEN : a1 / PEN;
            if ((mw >> (sh + 2)) & 1u) a2 = (a2 < 0.f) ? a2 * PEN : a2 / PEN;
            if ((mw >> (sh + 3)) & 1u) a3 = (a3 < 0.f) ? a3 * PEN : a3 / PEN;
        }
        a0 /= TEMP; a1 /= TEMP; a2 /= TEMP; a3 /= TEMP;
        __stcs(&o4[i], z4);
        if (a0 >= T0) { int p = atomicAdd(&g_cnt[row], 1); if (p < CAP) { g_cval[row][p] = a0; g_cidx[row][p] = base + j + 0; } }
        if (a1 >= T0) { int p = atomicAdd(&g_cnt[row], 1); if (p < CAP) { g_cval[row][p] = a1; g_cidx[row][p] = base + j + 1; } }
        if (a2 >= T0) { int p = atomicAdd(&g_cnt[row], 1); if (p < CAP) { g_cval[row][p] = a2; g_cidx[row][p] = base + j + 2; } }
        if (a3 >= T0) { int p = atomicAdd(&g_cnt[row], 1); if (p < CAP) { g_cval[row][p] = a3; g_cidx[row][p] = base + j + 3; } }
    }
}

// ============ K2: 2 rows per block (two independent 256-thread halves, one wave);
//               exact whole-block fallback for deficient rows; self-resets g_cnt ============
__global__ __launch_bounds__(NT) void finalize_kernel(
    const float* __restrict__ logits,
    const int*   __restrict__ prev,
    float*       __restrict__ out)
{
    __shared__ __align__(16) unsigned char ws[WS_BYTES];  // union: 2x fast WS | fallback arrays
    __shared__ float sm_top2[2][TOPSZ];
    __shared__ float sm_e2[2][TOPSZ];
    __shared__ int   sm_nk2[2], sm_m2[2], sm_need[2];
    __shared__ float sm_invZ2[2];
    // fallback whole-block scalars
    __shared__ int   sm_cnt, sm_bstar, sm_m, sm_nk;
    __shared__ float sm_v0, sm_invZ;

    const int tid  = threadIdx.x;
    const int half = tid >> 8;         // 0 or 1
    const int lt   = tid & 255;        // lane within half
    const int row  = (blockIdx.x << 1) + half;
    const int cnt  = g_cnt[row];
    float* orow = out + (size_t)row * V_;

    if (lt == 0) sm_need[half] = !(cnt >= TOPK && cnt <= CAP);

    if (cnt >= TOPK && cnt <= CAP) {
        // ---------- fast path (per-half, 256 threads) ----------
        float* cv = (float*)(ws + half * FAST_WS);           // CAP floats, 16B aligned
        int*   ci = (int*)(ws + half * FAST_WS + 4096);      // CAP ints
        short* rk = (short*)(ws + half * FAST_WS + 8192);    // CAP shorts
        const int n = cnt;

        for (int i = lt; i < n; i += 256) { cv[i] = g_cval[row][i]; ci[i] = g_cidx[row][i]; }
        BARH(half);

        // counting-rank with vocab-index tiebreak (== stable argsort desc), LDS.128 inner loop
        const float4* cv4 = (const float4*)cv;
        const int4*   ci4 = (const int4*)ci;
        const int n4 = n >> 2;
        for (int i = lt; i < n; i += 256) {
            float v = cv[i];
            int idx = ci[i];
            int r = 0;
            for (int k4 = 0; k4 < n4; k4++) {
                float4 w = cv4[k4];
                int4   d = ci4[k4];
                r += (w.x > v) || (w.x == v && d.x < idx);
                r += (w.y > v) || (w.y == v && d.y < idx);
                r += (w.z > v) || (w.z == v && d.z < idx);
                r += (w.w > v) || (w.w == v && d.w < idx);
            }
            for (int k = n4 << 2; k < n; k++) {
                float w = cv[k];
                r += (w > v) || (w == v && ci[k] < idx);
            }
            if (r < TOPSZ) sm_top2[half][r] = v;
            rk[i] = (short)(r < 32767 ? r : 32767);
        }
        BARH(half);

        // top-k tie extension (JAX keeps all values == 50th-largest)
        if (lt == 0) {
            float v50 = sm_top2[half][TOPK - 1];
            int lim = n < TOPSZ ? n : TOPSZ;
            int nk = TOPK;
            while (nk < lim && sm_top2[half][nk] == v50) nk++;
            sm_nk2[half] = nk;
            g_cnt[row] = 0;                          // reset for next replay
        }
        BARH(half);
        const int nk = sm_nk2[half];
        if (lt < nk) sm_e2[half][lt] = expf(sm_top2[half][lt] - sm_top2[half][0]);
        BARH(half);

        if (lt == 0) {
            float Z = 0.f;
            for (int i = 0; i < nk; i++) Z += sm_e2[half][i];
            float cum = 0.f, S = 0.f;
            int m = 0;
            for (int i = 0; i < nk; i++) {
                if (i > 0 && cum > TOPP) break;      // HF shift-right semantics
                cum += sm_e2[half][i] / Z;
                S   += sm_e2[half][i];
                m = i + 1;
            }
            sm_m2[half] = m; sm_invZ2[half] = 1.f / S;
        }
        BARH(half);

        const float invZ = sm_invZ2[half];
        const int m = sm_m2[half];
        for (int i = lt; i < n; i += 256) {
            int r = rk[i];
            if (r < m) orow[ci[i]] = sm_e2[half][r] * invZ;  // exp by rank (bitwise identical)
        }
    }

    __syncthreads();   // join: both halves done (or flagged)

    // ---------- exact whole-block fallback for flagged rows (rare) ----------
    #pragma unroll 1
    for (int h = 0; h < 2; h++) {
        if (!sm_need[h]) continue;
        __syncthreads();                              // arrays reuse boundary
        const int frow = (blockIdx.x << 1) + h;
        float* forow = out + (size_t)frow * V_;
        unsigned* f_mask  = (unsigned*)ws;            // 16000 B
        int*      f_hist  = (int*)(ws + 16000);       //  8192 B
        float*    f_cval  = (float*)(ws + 24192);     //  8192 B
        int*      f_cidx  = (int*)(ws + 32384);       //  8192 B
        int*      f_chunk = (int*)(ws + 40576);       //  2048 B
        const float4* __restrict__ l4 = (const float4*)(logits + (size_t)frow * V_);
        const int NV4 = V_ / 4;

        for (int i = tid; i < MASKW; i += NT) f_mask[i] = 0u;
        for (int i = tid; i < NBINS; i += NT) f_hist[i] = 0;
        if (tid == 0) { sm_cnt = 0; g_cnt[frow] = 0; }
        __syncthreads();
        for (int i = tid; i < H_; i += NT) {
            int t = prev[frow * H_ + i];
            atomicOr(&f_mask[((unsigned)t) >> 5], 1u << (t & 31));
        }
        __syncthreads();

        for (int i = tid; i < NV4; i += NT) {
            float4 v = l4[i];
            int j = i << 2;
            unsigned mw = f_mask[j >> 5];
            unsigned sh = j & 31;
            float a;
            a = v.x; if ((mw >> (sh + 0)) & 1u) a = (a < 0.f) ? a * PEN : a / PEN; a /= TEMP;
            atomicAdd(&f_hist[ordu(a) >> BSHIFT], 1);
            a = v.y; if ((mw >> (sh + 1)) & 1u) a = (a < 0.f) ? a * PEN : a / PEN; a /= TEMP;
            atomicAdd(&f_hist[ordu(a) >> BSHIFT], 1);
            a = v.z; if ((mw >> (sh + 2)) & 1u) a = (a < 0.f) ? a * PEN : a / PEN; a /= TEMP;
            atomicAdd(&f_hist[ordu(a) >> BSHIFT], 1);
            a = v.w; if ((mw >> (sh + 3)) & 1u) a = (a < 0.f) ? a * PEN : a / PEN; a /= TEMP;
            atomicAdd(&f_hist[ordu(a) >> BSHIFT], 1);
        }
        __syncthreads();

        {
            int s = 0;
            #pragma unroll
            for (int k = 0; k < BPC; k++) s += f_hist[tid * BPC + k];
            f_chunk[tid] = s;
            __syncthreads();
            for (int off = 1; off < NT; off <<= 1) {
                int add = (tid + off < NT) ? f_chunk[tid + off] : 0;
                __syncthreads();
                f_chunk[tid] += add;
                __syncthreads();
            }
            int myv = f_chunk[tid];
            int nxt = (tid + 1 < NT) ? f_chunk[tid + 1] : 0;
            if (myv >= TOPK && nxt < TOPK) {
                int run = nxt;
                int bstar = tid * BPC;
                for (int b = tid * BPC + BPC - 1; b >= tid * BPC; b--) {
                    run += f_hist[b];
                    if (run >= TOPK) { bstar = b; break; }
                }
                sm_bstar = bstar;
            }
        }
        __syncthreads();
        const unsigned uth = ((unsigned)sm_bstar) << BSHIFT;

        // reuse cval/cidx region as the candidate buffer (capacity limited to fit carve: 2048)
        for (int i = tid; i < NV4; i += NT) {
            float4 v = l4[i];
            int j = i << 2;
            unsigned mw = f_mask[j >> 5];
            unsigned sh = j & 31;
            float a0 = v.x; if ((mw >> (sh + 0)) & 1u) a0 = (a0 < 0.f) ? a0 * PEN : a0 / PEN; a0 /= TEMP;
            float a1 = v.y; if ((mw >> (sh + 1)) & 1u) a1 = (a1 < 0.f) ? a1 * PEN : a1 / PEN; a1 /= TEMP;
            float a2 = v.z; if ((mw >> (sh + 2)) & 1u) a2 = (a2 < 0.f) ? a2 * PEN : a2 / PEN; a2 /= TEMP;
            float a3 = v.w; if ((mw >> (sh + 3)) & 1u) a3 = (a3 < 0.f) ? a3 * PEN : a3 / PEN; a3 /= TEMP;
            if (ordu(a0) >= uth) { int p = atomicAdd(&sm_cnt, 1); if (p < CAPF) { f_cval[p] = a0; f_cidx[p] = j + 0; } }
            if (ordu(a1) >= uth) { int p = atomicAdd(&sm_cnt, 1); if (p < CAPF) { f_cval[p] = a1; f_cidx[p] = j + 1; } }
            if (ordu(a2) >= uth) { int p = atomicAdd(&sm_cnt, 1); if (p < CAPF) { f_cval[p] = a2; f_cidx[p] = j + 2; } }
            if (ordu(a3) >= uth) { int p = atomicAdd(&sm_cnt, 1); if (p < CAPF) { f_cval[p] = a3; f_cidx[p] = j + 3; } }
        }
        __syncthreads();
        const int n = sm_cnt < CAPF ? sm_cnt : CAPF;

        for (int i = tid; i < n; i += NT) {
            float v = f_cval[i];
            int idx = f_cidx[i] & IDXMASK;
            int r = 0;
            for (int k = 0; k < n; k++) {
                float w = f_cval[k];
                r += (w > v) || (w == v && (f_cidx[k] & IDXMASK) < idx);
            }
            if (r < TOPSZ) sm_top2[0][r] = v;
            int rc = r < 255 ? r : 255;
            f_cidx[i] = idx | (rc << 17);
        }
        __syncthreads();

        if (tid == 0) {
            float v50 = sm_top2[0][TOPK - 1];
            int lim = n < TOPSZ ? n : TOPSZ;
            int nk = TOPK;
            while (nk < lim && sm_top2[0][nk] == v50) nk++;
            float v0 = sm_top2[0][0];
            float Z = 0.f;
            for (int i = 0; i < nk; i++) { sm_e2[0][i] = expf(sm_top2[0][i] - v0); Z += sm_e2[0][i]; }
            float cum = 0.f, S = 0.f;
            int m = 0;
            for (int i = 0; i < nk; i++) {
                if (i > 0 && cum > TOPP) break;
                cum += sm_e2[0][i] / Z;
                S   += sm_e2[0][i];
                m = i + 1;
            }
            sm_v0 = v0; sm_m = m; sm_invZ = 1.f / S;
        }
        __syncthreads();

        {
            const float v0 = sm_v0, invZ = sm_invZ;
            const int m = sm_m;
            for (int i = tid; i < n; i += NT) {
                int packed = f_cidx[i];
                int r = packed >> 17;
                if (r < m) forow[packed & IDXMASK] = expf(f_cval[i] - v0) * invZ;
            }
        }
        __syncthreads();
    }
}

extern "C" void kernel_launch(void* const* d_in, const int* in_sizes, int n_in,
                              void* d_out, int out_size) {
    const float* logits = (const float*)d_in[0];
    const int*   prev   = (const int*)d_in[1];
    float*       out    = (float*)d_out;

    pass1_kernel<<<B_ * SPLIT, NT>>>(logits, prev, out);
    finalize_kernel<<<B_ / 2, NT>>>(logits, prev, out);
}